// round 1
// baseline (speedup 1.0000x reference)
#include <cuda_runtime.h>
#include <cstdint>

// Problem constants (fixed by the dataset)
#define MAXN 100000
#define DIN  64

// ---------------- scratch (no cudaMalloc allowed) ----------------
__device__ float g_PQ[(size_t)MAXN * 128];  // per-layer P|Q interleaved per node (also reused for layer3 [N,8])
__device__ float g_HA[(size_t)MAXN * 64];   // layer-1 output
__device__ float g_HB[(size_t)MAXN * 64];   // layer-2 output

// =================================================================
// GEMM: PQ[row, 0:64] = X@Wm ; PQ[row, 64:128] = X@Bm   (optionally relu(X))
// block = 256 threads, tile = 32 rows. tx = tid%64 (output col), ty = tid/64.
// =================================================================
template<bool RELU>
__global__ __launch_bounds__(256) void gemm_pq(const float* __restrict__ X,
                                               const float* __restrict__ Wm,
                                               const float* __restrict__ Bm,
                                               float* __restrict__ PQ, int N)
{
    __shared__ float sX[32 * 64];
    __shared__ float sWm[64 * 64];
    __shared__ float sBm[64 * 64];

    const int tid = threadIdx.x;
    const int tx = tid & 63;
    const int ty = tid >> 6;        // 0..3
    const int row0 = blockIdx.x * 32;

    // stage weights
    #pragma unroll
    for (int i = tid; i < 4096; i += 256) { sWm[i] = Wm[i]; sBm[i] = Bm[i]; }
    // stage X tile (coalesced)
    #pragma unroll
    for (int i = tid; i < 2048; i += 256) {
        int r = row0 + (i >> 6);
        float v = (r < N) ? X[(size_t)r * 64 + (i & 63)] : 0.f;
        if (RELU) v = fmaxf(v, 0.f);
        sX[i] = v;
    }
    __syncthreads();

    float accp[8], accq[8];
    #pragma unroll
    for (int r = 0; r < 8; r++) { accp[r] = 0.f; accq[r] = 0.f; }

    #pragma unroll 4
    for (int k = 0; k < 64; k++) {
        float wm = sWm[k * 64 + tx];
        float wb = sBm[k * 64 + tx];
        #pragma unroll
        for (int r = 0; r < 8; r++) {
            float xv = sX[(ty * 8 + r) * 64 + k];
            accp[r] = fmaf(xv, wm, accp[r]);
            accq[r] = fmaf(xv, wb, accq[r]);
        }
    }

    #pragma unroll
    for (int r = 0; r < 8; r++) {
        int row = row0 + ty * 8 + r;
        if (row < N) {
            PQ[(size_t)row * 128 + tx]      = accp[r];
            PQ[(size_t)row * 128 + 64 + tx] = accq[r];
        }
    }
}

// =================================================================
// GEMM: H[row, :] = X@Wr + bias   (optionally relu(X)) — root term init
// =================================================================
template<bool RELU>
__global__ __launch_bounds__(256) void gemm_r(const float* __restrict__ X,
                                              const float* __restrict__ Wr,
                                              const float* __restrict__ bias,
                                              float* __restrict__ H, int N)
{
    __shared__ float sX[32 * 64];
    __shared__ float sWr[64 * 64];
    __shared__ float sb[64];

    const int tid = threadIdx.x;
    const int tx = tid & 63;
    const int ty = tid >> 6;
    const int row0 = blockIdx.x * 32;

    #pragma unroll
    for (int i = tid; i < 4096; i += 256) sWr[i] = Wr[i];
    if (tid < 64) sb[tid] = bias[tid];
    #pragma unroll
    for (int i = tid; i < 2048; i += 256) {
        int r = row0 + (i >> 6);
        float v = (r < N) ? X[(size_t)r * 64 + (i & 63)] : 0.f;
        if (RELU) v = fmaxf(v, 0.f);
        sX[i] = v;
    }
    __syncthreads();

    float acc[8];
    #pragma unroll
    for (int r = 0; r < 8; r++) acc[r] = 0.f;

    #pragma unroll 4
    for (int k = 0; k < 64; k++) {
        float wr = sWr[k * 64 + tx];
        #pragma unroll
        for (int r = 0; r < 8; r++)
            acc[r] = fmaf(sX[(ty * 8 + r) * 64 + k], wr, acc[r]);
    }

    float b = sb[tx];
    #pragma unroll
    for (int r = 0; r < 8; r++) {
        int row = row0 + ty * 8 + r;
        if (row < N) H[(size_t)row * 64 + tx] = acc[r] + b;
    }
}

// =================================================================
// Edge scatter, d=64: H[dst] += e * P[src] + Q[src]
// 16 threads per edge, float4 each; vectorized red.global.add.v4.f32
// =================================================================
__global__ __launch_bounds__(256) void edge64_kernel(const int* __restrict__ ei,
                                                     const float* __restrict__ ea,
                                                     const float* __restrict__ PQ,
                                                     float* __restrict__ H, int E)
{
    int t = blockIdx.x * blockDim.x + threadIdx.x;
    int e = t >> 4;
    int l = t & 15;
    if (e >= E) return;

    int s = __ldg(ei + e);
    int d = __ldg(ei + E + e);
    float ev = __ldg(ea + e);

    const float4* pq = reinterpret_cast<const float4*>(PQ) + (size_t)s * 32;
    float4 p = __ldg(pq + l);
    float4 q = __ldg(pq + 16 + l);

    float4 m;
    m.x = fmaf(ev, p.x, q.x);
    m.y = fmaf(ev, p.y, q.y);
    m.z = fmaf(ev, p.z, q.z);
    m.w = fmaf(ev, p.w, q.w);

    float* out = H + (size_t)d * 64 + l * 4;
    asm volatile("red.global.add.v4.f32 [%0], {%1,%2,%3,%4};"
                 :: "l"(out), "f"(m.x), "f"(m.y), "f"(m.z), "f"(m.w)
                 : "memory");
}

// =================================================================
// Layer 3 GEMM (d_out=4): PQ3[row,0:4]=relu(X)@Wm, [4:8]=relu(X)@Bm,
// OUT[row,:] = relu(X)@Wr + b
// =================================================================
__global__ __launch_bounds__(256) void gemm3_kernel(const float* __restrict__ X,
                                                    const float* __restrict__ Wm,
                                                    const float* __restrict__ Bm,
                                                    const float* __restrict__ Wr,
                                                    const float* __restrict__ b,
                                                    float* __restrict__ PQ3,
                                                    float* __restrict__ OUT, int N)
{
    __shared__ float sw[768];   // [0:256) Wm, [256:512) Bm, [512:768) Wr  (k*4+c)
    int tid = threadIdx.x;
    if (tid < 256) { sw[tid] = Wm[tid]; sw[256 + tid] = Bm[tid]; sw[512 + tid] = Wr[tid]; }
    __syncthreads();

    int row = blockIdx.x * blockDim.x + tid;
    if (row >= N) return;

    float accp[4] = {0,0,0,0}, accq[4] = {0,0,0,0}, accr[4] = {0,0,0,0};
    const float* xr = X + (size_t)row * 64;
    #pragma unroll 4
    for (int k = 0; k < 64; k++) {
        float xv = fmaxf(__ldg(xr + k), 0.f);
        #pragma unroll
        for (int c = 0; c < 4; c++) {
            accp[c] = fmaf(xv, sw[k * 4 + c], accp[c]);
            accq[c] = fmaf(xv, sw[256 + k * 4 + c], accq[c]);
            accr[c] = fmaf(xv, sw[512 + k * 4 + c], accr[c]);
        }
    }
    #pragma unroll
    for (int c = 0; c < 4; c++) {
        PQ3[(size_t)row * 8 + c]     = accp[c];
        PQ3[(size_t)row * 8 + 4 + c] = accq[c];
        OUT[(size_t)row * 4 + c]     = accr[c] + b[c];
    }
}

// Edge scatter, d=4: one thread per edge
__global__ __launch_bounds__(256) void edge4_kernel(const int* __restrict__ ei,
                                                    const float* __restrict__ ea,
                                                    const float* __restrict__ PQ3,
                                                    float* __restrict__ OUT, int E)
{
    int e = blockIdx.x * blockDim.x + threadIdx.x;
    if (e >= E) return;
    int s = __ldg(ei + e);
    int d = __ldg(ei + E + e);
    float ev = __ldg(ea + e);

    const float4* pq = reinterpret_cast<const float4*>(PQ3) + (size_t)s * 2;
    float4 p = __ldg(pq);
    float4 q = __ldg(pq + 1);
    float4 m;
    m.x = fmaf(ev, p.x, q.x);
    m.y = fmaf(ev, p.y, q.y);
    m.z = fmaf(ev, p.z, q.z);
    m.w = fmaf(ev, p.w, q.w);

    float* out = OUT + (size_t)d * 4;
    asm volatile("red.global.add.v4.f32 [%0], {%1,%2,%3,%4};"
                 :: "l"(out), "f"(m.x), "f"(m.y), "f"(m.z), "f"(m.w)
                 : "memory");
}

// log_softmax over rows of 4, in place
__global__ __launch_bounds__(256) void logsoftmax4_kernel(float* __restrict__ OUT, int N)
{
    int row = blockIdx.x * blockDim.x + threadIdx.x;
    if (row >= N) return;
    float4 v = *reinterpret_cast<float4*>(OUT + (size_t)row * 4);
    float m = fmaxf(fmaxf(v.x, v.y), fmaxf(v.z, v.w));
    float s = __expf(v.x - m) + __expf(v.y - m) + __expf(v.z - m) + __expf(v.w - m);
    float lse = m + __logf(s);
    float4 o;
    o.x = v.x - lse; o.y = v.y - lse; o.z = v.z - lse; o.w = v.w - lse;
    *reinterpret_cast<float4*>(OUT + (size_t)row * 4) = o;
}

// =================================================================
extern "C" void kernel_launch(void* const* d_in, const int* in_sizes, int n_in,
                              void* d_out, int out_size)
{
    const float* x   = (const float*)d_in[0];
    const int*   ei  = (const int*)  d_in[1];   // [2, E] int32: src row then dst row
    const float* ea  = (const float*)d_in[2];   // [E, 1]
    const float* We1 = (const float*)d_in[3];
    const float* be1 = (const float*)d_in[4];
    const float* Wr1 = (const float*)d_in[5];
    const float* b1  = (const float*)d_in[6];
    const float* We2 = (const float*)d_in[7];
    const float* be2 = (const float*)d_in[8];
    const float* Wr2 = (const float*)d_in[9];
    const float* b2  = (const float*)d_in[10];
    const float* We3 = (const float*)d_in[11];
    const float* be3 = (const float*)d_in[12];
    const float* Wr3 = (const float*)d_in[13];
    const float* b3  = (const float*)d_in[14];

    const int N = in_sizes[0] / DIN;
    const int E = in_sizes[2];

    float *PQ, *HA, *HB;
    cudaGetSymbolAddress((void**)&PQ, g_PQ);
    cudaGetSymbolAddress((void**)&HA, g_HA);
    cudaGetSymbolAddress((void**)&HB, g_HB);
    float* OUT = (float*)d_out;

    const int gemmGrid = (N + 31) / 32;
    const int edge64Grid = (E * 16 + 255) / 256;
    const int rowGrid = (N + 255) / 256;
    const int edge4Grid = (E + 255) / 256;

    // ---- layer 1: X -> HA ----
    gemm_pq<false><<<gemmGrid, 256>>>(x, We1, be1, PQ, N);
    gemm_r<false><<<gemmGrid, 256>>>(x, Wr1, b1, HA, N);
    edge64_kernel<<<edge64Grid, 256>>>(ei, ea, PQ, HA, E);

    // ---- layer 2: relu(HA) -> HB ----
    gemm_pq<true><<<gemmGrid, 256>>>(HA, We2, be2, PQ, N);
    gemm_r<true><<<gemmGrid, 256>>>(HA, Wr2, b2, HB, N);
    edge64_kernel<<<edge64Grid, 256>>>(ei, ea, PQ, HB, E);

    // ---- layer 3: relu(HB) -> OUT, then log_softmax ----
    gemm3_kernel<<<rowGrid, 256>>>(HB, We3, be3, Wr3, b3, PQ, OUT, N);
    edge4_kernel<<<edge4Grid, 256>>>(ei, ea, PQ, OUT, E);
    logsoftmax4_kernel<<<rowGrid, 256>>>(OUT, N);
}